// round 1
// baseline (speedup 1.0000x reference)
#include <cuda_runtime.h>
#include <math.h>
#include <math_constants.h>

// Problem dims
#define S_LEN 256
#define BATCH 16
#define EDIM  512
#define HDIM  512
#define G4    2048   // 4*H
#define VDIM  32000

// Scratch (device globals; no allocations allowed)
__device__ float g_xp[(size_t)S_LEN * BATCH * G4];        // [S*B, 4H]  33.5 MB
__device__ float g_h[(size_t)(S_LEN + 1) * BATCH * HDIM]; // slot 0 = zeros, slot t+1 = h_t
__device__ float g_c[BATCH * HDIM];

// ---------------------------------------------------------------------------
// 0) zero initial state
// ---------------------------------------------------------------------------
__global__ void init_state() {
    int i = blockIdx.x * blockDim.x + threadIdx.x;
    if (i < BATCH * HDIM) {
        g_h[i] = 0.f;
        g_c[i] = 0.f;
    }
}

// ---------------------------------------------------------------------------
// 1) xp = gather(embed, tokens) @ W_ih^T + (b_ih + b_hh)
//    M=4096 (s*16+b), N=2048 (gate g), K=512 (e)
//    Tile 64x64x16, 256 threads, 4x4 per-thread.
// ---------------------------------------------------------------------------
__global__ void xp_gemm(const int* __restrict__ tokens,
                        const float* __restrict__ embed,
                        const float* __restrict__ W_ih,
                        const float* __restrict__ b_ih,
                        const float* __restrict__ b_hh) {
    __shared__ float A_s[16 * 65];
    __shared__ float B_s[16 * 65];
    __shared__ int tok_s[64];

    int tid = threadIdx.x;
    int m0 = blockIdx.y * 64;
    int n0 = blockIdx.x * 64;

    if (tid < 64) tok_s[tid] = tokens[m0 + tid];
    __syncthreads();

    int kcol = tid & 15;
    int rbase = tid >> 4;      // 0..15
    int ty = tid >> 4, tx = tid & 15;

    float acc[4][4] = {};

    for (int k0 = 0; k0 < EDIM; k0 += 16) {
#pragma unroll
        for (int i = 0; i < 4; i++) {
            int r = rbase + i * 16;
            A_s[kcol * 65 + r] = embed[(size_t)tok_s[r] * EDIM + k0 + kcol];
            B_s[kcol * 65 + r] = W_ih[(size_t)(n0 + r) * EDIM + k0 + kcol];
        }
        __syncthreads();
#pragma unroll
        for (int kk = 0; kk < 16; kk++) {
            float a[4], b[4];
#pragma unroll
            for (int i = 0; i < 4; i++) a[i] = A_s[kk * 65 + ty * 4 + i];
#pragma unroll
            for (int j = 0; j < 4; j++) b[j] = B_s[kk * 65 + tx * 4 + j];
#pragma unroll
            for (int i = 0; i < 4; i++)
#pragma unroll
                for (int j = 0; j < 4; j++)
                    acc[i][j] += a[i] * b[j];
        }
        __syncthreads();
    }

#pragma unroll
    for (int i = 0; i < 4; i++) {
        int m = m0 + ty * 4 + i;
#pragma unroll
        for (int j = 0; j < 4; j++) {
            int g = n0 + tx * 4 + j;
            g_xp[(size_t)m * G4 + g] = acc[i][j] + b_ih[g] + b_hh[g];
        }
    }
}

// ---------------------------------------------------------------------------
// 2) One LSTM timestep. grid = 128 CTAs x 256 threads.
//    CTA bx owns hidden units j0 = bx*4 .. bx*4+3, computing all 4 gates for
//    them (so the c/h pointwise update is CTA-local).
//    thread tid: b = tid%16, row_local rl = tid/16 in [0,16): rl = q*4+jj.
//    Dot over K=512 with W rows + h both staged in padded smem.
// ---------------------------------------------------------------------------
#define STEP_SMEM_FLOATS (2 * 512 * 17 + 16 * 17)
#define STEP_SMEM_BYTES  (STEP_SMEM_FLOATS * 4)

__global__ void lstm_step(const float* __restrict__ W_hh, int t) {
    extern __shared__ float sm[];
    float* wsT = sm;              // [512][17]: wsT[k*17 + rl]
    float* hs  = sm + 512 * 17;   // [512][17]: hs[k*17 + b]
    float* gs  = sm + 2 * 512 * 17; // [16][17]

    int tid = threadIdx.x;
    int j0 = blockIdx.x * 4;
    const float* hprev = g_h + (size_t)t * BATCH * HDIM;

    // Stage the 16 W_hh rows this CTA needs (rows q*512 + j0 + jj)
    for (int idx = tid; idx < 16 * 512; idx += 256) {
        int rl = idx >> 9;          // 0..15
        int k = idx & 511;
        int row = (rl >> 2) * 512 + j0 + (rl & 3);
        wsT[k * 17 + rl] = W_hh[(size_t)row * HDIM + k];
    }
    // Stage h_prev transposed: hs[k][b]
    for (int idx = tid; idx < BATCH * HDIM; idx += 256) {
        int b = idx >> 9;
        int k = idx & 511;
        hs[k * 17 + b] = hprev[idx];
    }
    __syncthreads();

    int b = tid & 15;
    int rl = tid >> 4;

    float acc = 0.f;
#pragma unroll 8
    for (int k = 0; k < 512; k++)
        acc = fmaf(wsT[k * 17 + rl], hs[k * 17 + b], acc);

    int q = rl >> 2, jj = rl & 3;
    int row = q * 512 + j0 + jj;
    float gate = acc + g_xp[((size_t)t * BATCH + b) * G4 + row];
    gs[rl * 17 + b] = gate;
    __syncthreads();

    if (tid < 64) {
        int jj2 = tid >> 4;     // 0..3
        int b2 = tid & 15;
        float ig = gs[(0 + jj2) * 17 + b2];
        float fg = gs[(4 + jj2) * 17 + b2];
        float gg = gs[(8 + jj2) * 17 + b2];
        float og = gs[(12 + jj2) * 17 + b2];
        int j = j0 + jj2;
        int ci = b2 * HDIM + j;
        float c = g_c[ci];
        float si = 1.f / (1.f + expf(-ig));
        float sf = 1.f / (1.f + expf(-fg));
        float so = 1.f / (1.f + expf(-og));
        float cn = sf * c + si * tanhf(gg);
        float hn = so * tanhf(cn);
        g_c[ci] = cn;
        g_h[(size_t)(t + 1) * BATCH * HDIM + ci] = hn;
    }
}

// ---------------------------------------------------------------------------
// 3) logits = Hs[4096,512] @ W_lin^T[512,32000] + b_lin  -> d_out
//    Tile 128x128x8, 256 threads, 8x8 per-thread register blocking.
// ---------------------------------------------------------------------------
__global__ void logits_gemm(const float* __restrict__ W_lin,
                            const float* __restrict__ b_lin,
                            float* __restrict__ out) {
    __shared__ __align__(16) float A_s[8 * 132];
    __shared__ __align__(16) float B_s[8 * 132];

    const float* A = g_h + BATCH * HDIM;  // rows 1..S of h history == Hs[m][k]

    int tid = threadIdx.x;
    int m0 = blockIdx.y * 128;
    int n0 = blockIdx.x * 128;

    int kcol = tid & 7;
    int rbase = tid >> 3;  // 0..31
    int ty = tid >> 4, tx = tid & 15;

    float acc[8][8] = {};

    for (int k0 = 0; k0 < HDIM; k0 += 8) {
#pragma unroll
        for (int i = 0; i < 4; i++) {
            int r = rbase + i * 32;
            A_s[kcol * 132 + r] = A[(size_t)(m0 + r) * HDIM + k0 + kcol];
            B_s[kcol * 132 + r] = W_lin[(size_t)(n0 + r) * HDIM + k0 + kcol];
        }
        __syncthreads();
#pragma unroll
        for (int kk = 0; kk < 8; kk++) {
            float4 a0 = *(const float4*)&A_s[kk * 132 + ty * 8];
            float4 a1 = *(const float4*)&A_s[kk * 132 + ty * 8 + 4];
            float4 b0 = *(const float4*)&B_s[kk * 132 + tx * 8];
            float4 b1 = *(const float4*)&B_s[kk * 132 + tx * 8 + 4];
            float a[8] = {a0.x, a0.y, a0.z, a0.w, a1.x, a1.y, a1.z, a1.w};
            float bb[8] = {b0.x, b0.y, b0.z, b0.w, b1.x, b1.y, b1.z, b1.w};
#pragma unroll
            for (int i = 0; i < 8; i++)
#pragma unroll
                for (int j = 0; j < 8; j++)
                    acc[i][j] = fmaf(a[i], bb[j], acc[i][j]);
        }
        __syncthreads();
    }

#pragma unroll
    for (int i = 0; i < 8; i++) {
        int m = m0 + ty * 8 + i;
        float* orow = out + (size_t)m * VDIM + n0 + tx * 8;
        float4 o0, o1;
        o0.x = acc[i][0] + b_lin[n0 + tx * 8 + 0];
        o0.y = acc[i][1] + b_lin[n0 + tx * 8 + 1];
        o0.z = acc[i][2] + b_lin[n0 + tx * 8 + 2];
        o0.w = acc[i][3] + b_lin[n0 + tx * 8 + 3];
        o1.x = acc[i][4] + b_lin[n0 + tx * 8 + 4];
        o1.y = acc[i][5] + b_lin[n0 + tx * 8 + 5];
        o1.z = acc[i][6] + b_lin[n0 + tx * 8 + 6];
        o1.w = acc[i][7] + b_lin[n0 + tx * 8 + 7];
        *(float4*)(orow)     = o0;
        *(float4*)(orow + 4) = o1;
    }
}

// ---------------------------------------------------------------------------
// 4) in-place log_softmax over V per (s,b) row. 1 CTA / row; row stays in L2
//    between the three passes.
// ---------------------------------------------------------------------------
__global__ void logsoftmax_rows(float* __restrict__ out) {
    __shared__ float red[256];
    int row = blockIdx.x;
    float* x = out + (size_t)row * VDIM;
    int tid = threadIdx.x;

    float m = -CUDART_INF_F;
    for (int i = tid; i < VDIM; i += 256) m = fmaxf(m, x[i]);
    red[tid] = m;
    __syncthreads();
    for (int s2 = 128; s2 > 0; s2 >>= 1) {
        if (tid < s2) red[tid] = fmaxf(red[tid], red[tid + s2]);
        __syncthreads();
    }
    m = red[0];
    __syncthreads();

    float s = 0.f;
    for (int i = tid; i < VDIM; i += 256) s += expf(x[i] - m);
    red[tid] = s;
    __syncthreads();
    for (int s2 = 128; s2 > 0; s2 >>= 1) {
        if (tid < s2) red[tid] += red[tid + s2];
        __syncthreads();
    }
    float lse = m + logf(red[0]);

    for (int i = tid; i < VDIM; i += 256) x[i] = x[i] - lse;
}

// ---------------------------------------------------------------------------
// launch
// ---------------------------------------------------------------------------
extern "C" void kernel_launch(void* const* d_in, const int* in_sizes, int n_in,
                              void* d_out, int out_size) {
    const int*   tokens = (const int*)d_in[0];
    // d_in[1] = input_lengths (unused by the reference output)
    const float* embed  = (const float*)d_in[2];
    const float* W_ih   = (const float*)d_in[3];
    const float* W_hh   = (const float*)d_in[4];
    const float* b_ih   = (const float*)d_in[5];
    const float* b_hh   = (const float*)d_in[6];
    const float* W_lin  = (const float*)d_in[7];
    const float* b_lin  = (const float*)d_in[8];
    float* out = (float*)d_out;

    cudaFuncSetAttribute(lstm_step, cudaFuncAttributeMaxDynamicSharedMemorySize,
                         STEP_SMEM_BYTES);

    init_state<<<32, 256>>>();
    xp_gemm<<<dim3(G4 / 64, (S_LEN * BATCH) / 64), 256>>>(tokens, embed, W_ih, b_ih, b_hh);
    for (int t = 0; t < S_LEN; t++)
        lstm_step<<<128, 256, STEP_SMEM_BYTES>>>(W_hh, t);
    logits_gemm<<<dim3(VDIM / 128, (S_LEN * BATCH) / 128), 256>>>(W_lin, b_lin, out);
    logsoftmax_rows<<<S_LEN * BATCH, 256>>>(out);
}

// round 2
// speedup vs baseline: 1.2961x; 1.2961x over previous
#include <cuda_runtime.h>
#include <math.h>
#include <math_constants.h>

// Problem dims
#define S_LEN 256
#define BATCH 16
#define EDIM  512
#define HDIM  512
#define G4    2048   // 4*H
#define VDIM  32000
#define NCTA  128    // persistent LSTM grid

// Scratch (device globals; no allocations allowed)
__device__ float g_xp[(size_t)S_LEN * BATCH * G4];        // [S*B, 4H]
__device__ float g_h[(size_t)(S_LEN + 1) * BATCH * HDIM]; // slot 0 = zeros, slot t+1 = h_t
__device__ int   g_bar_cnt;
__device__ volatile int g_bar_epoch;

// ---------------------------------------------------------------------------
// 0) zero initial state + barrier bookkeeping (runs every graph replay)
// ---------------------------------------------------------------------------
__global__ void init_state() {
    int i = blockIdx.x * blockDim.x + threadIdx.x;
    if (i < BATCH * HDIM) g_h[i] = 0.f;
    if (i == 0) { g_bar_cnt = 0; g_bar_epoch = 0; }
}

// ---------------------------------------------------------------------------
// 1) xp = gather(embed, tokens) @ W_ih^T + (b_ih + b_hh)
//    M=4096, N=2048, K=512. Tile 64x64x16, 256 threads, 4x4 per-thread.
// ---------------------------------------------------------------------------
__global__ void xp_gemm(const int* __restrict__ tokens,
                        const float* __restrict__ embed,
                        const float* __restrict__ W_ih,
                        const float* __restrict__ b_ih,
                        const float* __restrict__ b_hh) {
    __shared__ float A_s[16 * 65];
    __shared__ float B_s[16 * 65];
    __shared__ int tok_s[64];

    int tid = threadIdx.x;
    int m0 = blockIdx.y * 64;
    int n0 = blockIdx.x * 64;

    if (tid < 64) tok_s[tid] = tokens[m0 + tid];
    __syncthreads();

    int kcol = tid & 15;
    int rbase = tid >> 4;
    int ty = tid >> 4, tx = tid & 15;

    float acc[4][4] = {};

    for (int k0 = 0; k0 < EDIM; k0 += 16) {
#pragma unroll
        for (int i = 0; i < 4; i++) {
            int r = rbase + i * 16;
            A_s[kcol * 65 + r] = embed[(size_t)tok_s[r] * EDIM + k0 + kcol];
            B_s[kcol * 65 + r] = W_ih[(size_t)(n0 + r) * EDIM + k0 + kcol];
        }
        __syncthreads();
#pragma unroll
        for (int kk = 0; kk < 16; kk++) {
            float a[4], b[4];
#pragma unroll
            for (int i = 0; i < 4; i++) a[i] = A_s[kk * 65 + ty * 4 + i];
#pragma unroll
            for (int j = 0; j < 4; j++) b[j] = B_s[kk * 65 + tx * 4 + j];
#pragma unroll
            for (int i = 0; i < 4; i++)
#pragma unroll
                for (int j = 0; j < 4; j++)
                    acc[i][j] += a[i] * b[j];
        }
        __syncthreads();
    }

#pragma unroll
    for (int i = 0; i < 4; i++) {
        int m = m0 + ty * 4 + i;
#pragma unroll
        for (int j = 0; j < 4; j++) {
            int g = n0 + tx * 4 + j;
            g_xp[(size_t)m * G4 + g] = acc[i][j] + b_ih[g] + b_hh[g];
        }
    }
}

// ---------------------------------------------------------------------------
// 2) Persistent LSTM: one kernel, 256 steps, global barrier between steps.
//    128 CTAs x 256 threads. CTA owns hidden units j0..j0+3 across all 4
//    gates (16 W_hh rows, staged in smem ONCE). c lives in smem.
//
//    Compute mapping: tid = ks*64 + rl*4 + bq
//      ks in [0,4): k-range [ks*128, ks*128+128)
//      rl in [0,16): W row  (gate q = rl>>2, unit jj = rl&3)
//      bq in [0,4): batches b = {bq, bq+4, bq+8, bq+12}
//    float4 over k for both operands; strides padded to 516 floats so all
//    smem wavefronts are conflict-free.
// ---------------------------------------------------------------------------
#define WS_STRIDE 516
#define SM_WS   0
#define SM_HS   (16 * WS_STRIDE)                 // 8256
#define SM_PS   (SM_HS + 16 * WS_STRIDE)         // 16512  psum[4][16][17]
#define SM_GS   (SM_PS + 4 * 16 * 17)            // 17600  gsm[16][17]
#define SM_CS   (SM_GS + 16 * 17)                // 17872  csm[64]
#define SM_TOT  (SM_CS + 64)                     // 17936 floats
#define LSTM_SMEM_BYTES (SM_TOT * 4)

__global__ void __launch_bounds__(256, 1) lstm_persist(const float* __restrict__ W_hh) {
    extern __shared__ float sm[];
    float* ws   = sm + SM_WS;
    float* hs   = sm + SM_HS;
    float* psum = sm + SM_PS;
    float* gsm  = sm + SM_GS;
    float* csm  = sm + SM_CS;

    int tid = threadIdx.x;
    int j0 = blockIdx.x * 4;

    // Stage this CTA's 16 W_hh rows once (row = q*512 + j0 + jj)
    for (int idx = tid; idx < 16 * 512; idx += 256) {
        int rl = idx >> 9, k = idx & 511;
        int row = (rl >> 2) * 512 + j0 + (rl & 3);
        ws[rl * WS_STRIDE + k] = W_hh[(size_t)row * HDIM + k];
    }
    if (tid < 64) csm[tid] = 0.f;

    // decode thread roles
    int ks = tid >> 6;
    int rl = (tid >> 2) & 15;
    int bq = tid & 3;
    int rlr = tid >> 4, br = tid & 15;              // reduction mapping
    int xprow = (rlr >> 2) * 512 + j0 + (rlr & 3);  // gate row for (rlr)

    const float* wp  = ws + rl * WS_STRIDE + ks * 128;
    const float* hp0 = hs + (bq + 0)  * WS_STRIDE + ks * 128;
    const float* hp1 = hs + (bq + 4)  * WS_STRIDE + ks * 128;
    const float* hp2 = hs + (bq + 8)  * WS_STRIDE + ks * 128;
    const float* hp3 = hs + (bq + 12) * WS_STRIDE + ks * 128;
    float* pw = psum + (ks * 16 + rl) * 17 + bq;

    __syncthreads();

    for (int t = 0; t < S_LEN; t++) {
        // stage h_t: 2048 float4, coalesced LDG -> smem [b][k]
        const float4* hsrc = (const float4*)(g_h + (size_t)t * BATCH * HDIM);
#pragma unroll
        for (int i = 0; i < 8; i++) {
            int idx = tid + i * 256;
            float4 v = hsrc[idx];
            int b = idx >> 7;
            int k = (idx & 127) << 2;
            *(float4*)&hs[b * WS_STRIDE + k] = v;
        }
        // prefetch xp for the reduction phase
        float xpv = g_xp[((size_t)t * BATCH + br) * G4 + xprow];
        __syncthreads();

        // main dot products: 512 FMA / thread, all float4 LDS, conflict-free
        float a0 = 0.f, a1 = 0.f, a2 = 0.f, a3 = 0.f;
#pragma unroll 8
        for (int k = 0; k < 128; k += 4) {
            float4 w  = *(const float4*)(wp + k);
            float4 h0 = *(const float4*)(hp0 + k);
            float4 h1 = *(const float4*)(hp1 + k);
            float4 h2 = *(const float4*)(hp2 + k);
            float4 h3 = *(const float4*)(hp3 + k);
            a0 = fmaf(w.x, h0.x, a0); a0 = fmaf(w.y, h0.y, a0);
            a0 = fmaf(w.z, h0.z, a0); a0 = fmaf(w.w, h0.w, a0);
            a1 = fmaf(w.x, h1.x, a1); a1 = fmaf(w.y, h1.y, a1);
            a1 = fmaf(w.z, h1.z, a1); a1 = fmaf(w.w, h1.w, a1);
            a2 = fmaf(w.x, h2.x, a2); a2 = fmaf(w.y, h2.y, a2);
            a2 = fmaf(w.z, h2.z, a2); a2 = fmaf(w.w, h2.w, a2);
            a3 = fmaf(w.x, h3.x, a3); a3 = fmaf(w.y, h3.y, a3);
            a3 = fmaf(w.z, h3.z, a3); a3 = fmaf(w.w, h3.w, a3);
        }
        pw[0]  = a0;   // b = bq
        pw[4]  = a1;   // b = bq+4
        pw[8]  = a2;   // b = bq+8
        pw[12] = a3;   // b = bq+12
        __syncthreads();

        // reduce over ks and add xp -> gate[rlr][br]
        float gate = psum[(0 * 16 + rlr) * 17 + br]
                   + psum[(1 * 16 + rlr) * 17 + br]
                   + psum[(2 * 16 + rlr) * 17 + br]
                   + psum[(3 * 16 + rlr) * 17 + br]
                   + xpv;
        gsm[rlr * 17 + br] = gate;
        __syncthreads();

        // pointwise c/h update for this CTA's 4 units x 16 batches
        if (tid < 64) {
            int jj2 = tid >> 4, b2 = tid & 15;
            float ig = gsm[(0  + jj2) * 17 + b2];
            float fg = gsm[(4  + jj2) * 17 + b2];
            float gg = gsm[(8  + jj2) * 17 + b2];
            float og = gsm[(12 + jj2) * 17 + b2];
            float c = csm[tid];
            float si = 1.f / (1.f + expf(-ig));
            float sf = 1.f / (1.f + expf(-fg));
            float so = 1.f / (1.f + expf(-og));
            float cn = sf * c + si * tanhf(gg);
            float hn = so * tanhf(cn);
            csm[tid] = cn;
            g_h[(size_t)(t + 1) * BATCH * HDIM + (size_t)b2 * HDIM + j0 + jj2] = hn;
        }

        // global barrier: make h visible, arrive, wait for all 128 CTAs
        __threadfence();
        __syncthreads();
        if (tid == 0) {
            int old = atomicAdd(&g_bar_cnt, 1);
            if (old == (t + 1) * NCTA - 1) {
                g_bar_epoch = t + 1;
            } else {
                while (g_bar_epoch < t + 1) __nanosleep(64);
            }
        }
        __syncthreads();
    }
}

// ---------------------------------------------------------------------------
// 3) logits = Hs[4096,512] @ W_lin^T[512,32000] + b_lin  -> d_out
//    Tile 128x128x8, 256 threads, 8x8 per-thread register blocking.
// ---------------------------------------------------------------------------
__global__ void logits_gemm(const float* __restrict__ W_lin,
                            const float* __restrict__ b_lin,
                            float* __restrict__ out) {
    __shared__ __align__(16) float A_s[8 * 132];
    __shared__ __align__(16) float B_s[8 * 132];

    const float* A = g_h + BATCH * HDIM;  // rows 1..S of h history == Hs[m][k]

    int tid = threadIdx.x;
    int m0 = blockIdx.y * 128;
    int n0 = blockIdx.x * 128;

    int kcol = tid & 7;
    int rbase = tid >> 3;
    int ty = tid >> 4, tx = tid & 15;

    float acc[8][8] = {};

    for (int k0 = 0; k0 < HDIM; k0 += 8) {
#pragma unroll
        for (int i = 0; i < 4; i++) {
            int r = rbase + i * 32;
            A_s[kcol * 132 + r] = A[(size_t)(m0 + r) * HDIM + k0 + kcol];
            B_s[kcol * 132 + r] = W_lin[(size_t)(n0 + r) * HDIM + k0 + kcol];
        }
        __syncthreads();
#pragma unroll
        for (int kk = 0; kk < 8; kk++) {
            float4 a0 = *(const float4*)&A_s[kk * 132 + ty * 8];
            float4 a1 = *(const float4*)&A_s[kk * 132 + ty * 8 + 4];
            float4 b0 = *(const float4*)&B_s[kk * 132 + tx * 8];
            float4 b1 = *(const float4*)&B_s[kk * 132 + tx * 8 + 4];
            float a[8] = {a0.x, a0.y, a0.z, a0.w, a1.x, a1.y, a1.z, a1.w};
            float bb[8] = {b0.x, b0.y, b0.z, b0.w, b1.x, b1.y, b1.z, b1.w};
#pragma unroll
            for (int i = 0; i < 8; i++)
#pragma unroll
                for (int j = 0; j < 8; j++)
                    acc[i][j] = fmaf(a[i], bb[j], acc[i][j]);
        }
        __syncthreads();
    }

#pragma unroll
    for (int i = 0; i < 8; i++) {
        int m = m0 + ty * 8 + i;
        float* orow = out + (size_t)m * VDIM + n0 + tx * 8;
        float4 o0, o1;
        o0.x = acc[i][0] + b_lin[n0 + tx * 8 + 0];
        o0.y = acc[i][1] + b_lin[n0 + tx * 8 + 1];
        o0.z = acc[i][2] + b_lin[n0 + tx * 8 + 2];
        o0.w = acc[i][3] + b_lin[n0 + tx * 8 + 3];
        o1.x = acc[i][4] + b_lin[n0 + tx * 8 + 4];
        o1.y = acc[i][5] + b_lin[n0 + tx * 8 + 5];
        o1.z = acc[i][6] + b_lin[n0 + tx * 8 + 6];
        o1.w = acc[i][7] + b_lin[n0 + tx * 8 + 7];
        *(float4*)(orow)     = o0;
        *(float4*)(orow + 4) = o1;
    }
}

// ---------------------------------------------------------------------------
// 4) in-place log_softmax over V per (s,b) row.
// ---------------------------------------------------------------------------
__global__ void logsoftmax_rows(float* __restrict__ out) {
    __shared__ float red[256];
    int row = blockIdx.x;
    float* x = out + (size_t)row * VDIM;
    int tid = threadIdx.x;

    float m = -CUDART_INF_F;
    for (int i = tid; i < VDIM; i += 256) m = fmaxf(m, x[i]);
    red[tid] = m;
    __syncthreads();
    for (int s2 = 128; s2 > 0; s2 >>= 1) {
        if (tid < s2) red[tid] = fmaxf(red[tid], red[tid + s2]);
        __syncthreads();
    }
    m = red[0];
    __syncthreads();

    float s = 0.f;
    for (int i = tid; i < VDIM; i += 256) s += expf(x[i] - m);
    red[tid] = s;
    __syncthreads();
    for (int s2 = 128; s2 > 0; s2 >>= 1) {
        if (tid < s2) red[tid] += red[tid + s2];
        __syncthreads();
    }
    float lse = m + logf(red[0]);

    for (int i = tid; i < VDIM; i += 256) x[i] = x[i] - lse;
}

// ---------------------------------------------------------------------------
// launch
// ---------------------------------------------------------------------------
extern "C" void kernel_launch(void* const* d_in, const int* in_sizes, int n_in,
                              void* d_out, int out_size) {
    const int*   tokens = (const int*)d_in[0];
    // d_in[1] = input_lengths (unused by the reference output)
    const float* embed  = (const float*)d_in[2];
    const float* W_ih   = (const float*)d_in[3];
    const float* W_hh   = (const float*)d_in[4];
    const float* b_ih   = (const float*)d_in[5];
    const float* b_hh   = (const float*)d_in[6];
    const float* W_lin  = (const float*)d_in[7];
    const float* b_lin  = (const float*)d_in[8];
    float* out = (float*)d_out;

    cudaFuncSetAttribute(lstm_persist, cudaFuncAttributeMaxDynamicSharedMemorySize,
                         LSTM_SMEM_BYTES);

    init_state<<<32, 256>>>();
    xp_gemm<<<dim3(G4 / 64, (S_LEN * BATCH) / 64), 256>>>(tokens, embed, W_ih, b_ih, b_hh);
    lstm_persist<<<NCTA, 256, LSTM_SMEM_BYTES>>>(W_hh);
    logits_gemm<<<dim3(VDIM / 128, (S_LEN * BATCH) / 128), 256>>>(W_lin, b_lin, out);
    logsoftmax_rows<<<S_LEN * BATCH, 256>>>(out);
}